// round 5
// baseline (speedup 1.0000x reference)
#include <cuda_runtime.h>
#include <cuda_bf16.h>
#include <math.h>
#include <float.h>

#define NROWS 65536      // 32*32*64
#define DIM   64
#define NE    1024
#define LDE   65         // vq_pairs tile ld

// Output layout (float32, return-order flatten)
#define ZQ_OFF   1
#define PERP_OFF (1 + NROWS*DIM)
#define IDX_OFF  (2 + NROWS*DIM)

#define DELTA 4e-5f      // ambiguity margin (> 2*approx_err + ulp(64) window)
#define LDA   136        // padded split-row ld in bf16 (272B = 17*16B: 16B-aligned, odd seg stride)

// ---- scratch (no allocations allowed) ----
__device__ float  g_counts[NE];
__device__ float  g_en[NE];
__device__ float  g_zsq[NROWS];
__device__ int    g_idx[NROWS];
__device__ int    g_amb_rows[NROWS];
__device__ int    g_amb_cnt;
__device__ double g_mse;
__device__ double g_edist;
__device__ __nv_bfloat16 g_esplit[NE * 128];       // [code][ eh(64) | el(64) ]
__device__ __nv_bfloat16 g_zsplit[NROWS * 128];    // [row ][ zh(64) | zl(64) ]

// ============================================================
// PTX helpers
// ============================================================
__device__ __forceinline__ void ldmx4(unsigned* r, unsigned addr) {
    asm volatile("ldmatrix.sync.aligned.m8n8.x4.shared.b16 {%0,%1,%2,%3}, [%4];"
                 : "=r"(r[0]), "=r"(r[1]), "=r"(r[2]), "=r"(r[3]) : "r"(addr));
}
__device__ __forceinline__ void ldmx2(unsigned* r, unsigned addr) {
    asm volatile("ldmatrix.sync.aligned.m8n8.x2.shared.b16 {%0,%1}, [%2];"
                 : "=r"(r[0]), "=r"(r[1]) : "r"(addr));
}
__device__ __forceinline__ void mma16816(float* c, const unsigned* a, const unsigned* b) {
    asm volatile("mma.sync.aligned.m16n8k16.row.col.f32.bf16.bf16.f32 "
                 "{%0,%1,%2,%3}, {%4,%5,%6,%7}, {%8,%9}, {%0,%1,%2,%3};"
                 : "+f"(c[0]), "+f"(c[1]), "+f"(c[2]), "+f"(c[3])
                 : "r"(a[0]), "r"(a[1]), "r"(a[2]), "r"(a[3]), "r"(b[0]), "r"(b[1]));
}

// ============================================================
// init: zero accumulators, exact ||e||^2 (sequential UNFUSED),
// and the bf16 split of the codebook.
// ============================================================
__global__ void vq_init(const float* __restrict__ emb) {
    int t = threadIdx.x;           // 1024 threads = codes
    if (t == 0) { g_mse = 0.0; g_edist = 0.0; g_amb_cnt = 0; }
    g_counts[t] = 0.0f;
    const float* e = emb + t * DIM;
    float s = 0.0f;
#pragma unroll
    for (int k = 0; k < DIM; k++) {
        float sq = __fmul_rn(e[k], e[k]);
        s = __fadd_rn(s, sq);
        __nv_bfloat16 h = __float2bfloat16(e[k]);
        __nv_bfloat16 l = __float2bfloat16(e[k] - __bfloat162float(h));
        g_esplit[t * 128 + k]      = h;
        g_esplit[t * 128 + 64 + k] = l;
    }
    g_en[t] = s;
}

// ============================================================
// prep: exact ||z||^2 per row (sequential UNFUSED) + bf16 split.
// ============================================================
__global__ __launch_bounds__(256) void vq_prep(const float* __restrict__ z) {
    __shared__ float zs[64][65];
    int tid = threadIdx.x;
    int r0  = blockIdx.x * 64;
#pragma unroll
    for (int i = 0; i < 16; i++) {
        int idx = tid + i * 256;
        int r = idx >> 6, c = idx & 63;
        zs[r][c] = z[(r0 + r) * DIM + c];
    }
    __syncthreads();
    if (tid < 64) {
        float s = 0.0f;
#pragma unroll
        for (int k = 0; k < DIM; k++) {
            float sq = __fmul_rn(zs[tid][k], zs[tid][k]);
            s = __fadd_rn(s, sq);
        }
        g_zsq[r0 + tid] = s;
    }
#pragma unroll
    for (int i = 0; i < 16; i++) {
        int idx = tid + i * 256;
        int r = idx >> 6, c = idx & 63;
        float v = zs[r][c];
        __nv_bfloat16 h = __float2bfloat16(v);
        __nv_bfloat16 l = __float2bfloat16(v - __bfloat162float(h));
        g_zsplit[(r0 + r) * 128 + c]      = h;
        g_zsplit[(r0 + r) * 128 + 64 + c] = l;
    }
}

// ============================================================
// codebook pairwise distances (e_loss) — unchanged, validated.
// ============================================================
__global__ __launch_bounds__(256) void vq_pairs(const float* __restrict__ emb) {
    __shared__ float ei[8][DIM];
    __shared__ float ej[128][LDE];
    __shared__ float eni_s[8];
    __shared__ float red[8];
    int tid = threadIdx.x;
    int i0  = blockIdx.x * 8;

    for (int v = tid; v < 8 * DIM; v += 256)
        ei[v >> 6][v & 63] = emb[i0 * DIM + v];
    if (tid < 8) eni_s[tid] = g_en[i0 + tid];

    float sum = 0.0f;
    for (int jc = 0; jc < NE; jc += 128) {
        __syncthreads();
#pragma unroll
        for (int t = 0; t < 8; t++) {
            int v  = tid + t * 256;
            int jl = v >> 4, c4 = (v & 15) << 2;
            float4 f = *reinterpret_cast<const float4*>(emb + (jc + jl) * DIM + c4);
            ej[jl][c4 + 0] = f.x; ej[jl][c4 + 1] = f.y;
            ej[jl][c4 + 2] = f.z; ej[jl][c4 + 3] = f.w;
        }
        __syncthreads();
        int il = tid >> 5, lane = tid & 31;
#pragma unroll
        for (int jj = 0; jj < 4; jj++) {
            int jl = lane + 32 * jj;
            float dot = 0.0f;
#pragma unroll 16
            for (int k = 0; k < DIM; k++)
                dot = fmaf(ei[il][k], ej[jl][k], dot);
            float d2 = eni_s[il] + g_en[jc + jl] - 2.0f * dot;
            sum += sqrtf(fmaxf(d2, 0.0f));
        }
    }
#pragma unroll
    for (int off = 16; off > 0; off >>= 1)
        sum += __shfl_down_sync(0xffffffffu, sum, off);
    if ((tid & 31) == 0) red[tid >> 5] = sum;
    __syncthreads();
    if (tid == 0) {
        float s = 0.0f;
#pragma unroll
        for (int w = 0; w < 8; w++) s += red[w];
        atomicAdd(&g_edist, (double)s);
    }
}

// ============================================================
// filter: split-bf16 tensor-core scoring + per-row (min1,min2).
// CTA = 128 thr (4 warps x 32 rows) = 128 rows; codes in 4
// chunks of 256. K=192 synthesized from 128 split cols:
//   ks 0-3: zh*eh   ks 4-7: zh*el   ks 8-11: zl*eh
// u_j = en_j - 2*dot~_j;  min2-min1 < DELTA -> exact rescan.
// ============================================================
__global__ __launch_bounds__(128, 2) void vq_filter(void) {
    extern __shared__ __nv_bfloat16 sm[];
    __nv_bfloat16* As = sm;                        // [128][LDA]
    __nv_bfloat16* Bs = sm + 128 * LDA;            // [256][LDA]
    float* en_s = (float*)(sm + (128 + 256) * LDA);// [256]

    const int tid = threadIdx.x, lane = tid & 31, w = tid >> 5;
    const int m0 = blockIdx.x * 128;

    // stage A (zsplit rows) into padded smem
    const unsigned* zsp = (const unsigned*)g_zsplit;
#pragma unroll
    for (int i = 0; i < 64; i++) {                 // 8192 uints / 128 thr
        int idx = tid + i * 128;
        int r = idx >> 6, c2 = idx & 63;
        *(unsigned*)((char*)As + (r * LDA + 2 * c2) * 2) = zsp[(m0 + r) * 64 + c2];
    }
    __syncthreads();

    // A fragments: 8 distinct (zh k0..63 -> f0-3, zl -> f4-7) x 2 mtiles
    unsigned afr[8][2][4];
    unsigned abase = (unsigned)__cvta_generic_to_shared(As);
#pragma unroll
    for (int f = 0; f < 8; f++) {
        int aoff = (f < 4) ? 16 * f : 64 + 16 * (f - 4);
#pragma unroll
        for (int m = 0; m < 2; m++) {
            int row = w * 32 + m * 16 + (lane & 15);
            int col = aoff + (lane >> 4) * 8;
            ldmx4(afr[f][m], abase + (unsigned)(row * LDA + col) * 2u);
        }
    }

    float m1v[4], m2v[4]; int m1i[4];
#pragma unroll
    for (int s = 0; s < 4; s++) { m1v[s] = FLT_MAX; m2v[s] = FLT_MAX; m1i[s] = 0; }

    unsigned bbase = (unsigned)__cvta_generic_to_shared(Bs);
    const unsigned* esp = (const unsigned*)g_esplit;

    for (int ch = 0; ch < 4; ch++) {
        const int cb = ch * 256;
        __syncthreads();                           // Bs free from previous chunk
#pragma unroll 4
        for (int i = 0; i < 128; i++) {            // 16384 uints / 128 thr
            int idx = tid + i * 128;
            int r = idx >> 6, c2 = idx & 63;
            *(unsigned*)((char*)Bs + (r * LDA + 2 * c2) * 2) = esp[(cb + r) * 64 + c2];
        }
        en_s[tid]       = g_en[cb + tid];
        en_s[tid + 128] = g_en[cb + tid + 128];
        __syncthreads();

#pragma unroll 1
        for (int nt = 0; nt < 32; nt++) {
            float acc[2][4];
#pragma unroll
            for (int m = 0; m < 2; m++)
#pragma unroll
                for (int q = 0; q < 4; q++) acc[m][q] = 0.0f;

            const int brow = nt * 8 + (lane & 7);
            const int bsel = ((lane >> 3) & 1) * 8;
#pragma unroll
            for (int ks = 0; ks < 12; ks++) {
                int f    = (ks < 8) ? (ks & 3) : (4 + (ks & 3));
                int boff = (ks < 4) ? 16 * ks : (ks < 8) ? 64 + 16 * (ks - 4) : 16 * (ks - 8);
                unsigned bf[2];
                ldmx2(bf, bbase + (unsigned)(brow * LDA + boff + bsel) * 2u);
                mma16816(acc[0], afr[f][0], bf);
                mma16816(acc[1], afr[f][1], bf);
            }

            int c0 = nt * 8 + (lane & 3) * 2;
            float en0 = en_s[c0], en1 = en_s[c0 + 1];
            int g0 = cb + c0;
            // slot s -> row (lane>>2) + 8*s; value pair = acc[s>>1][(s&1)*2 .. +1]
#pragma unroll
            for (int s = 0; s < 4; s++) {
                float u0 = fmaf(-2.0f, acc[s >> 1][(s & 1) * 2],     en0);
                float u1 = fmaf(-2.0f, acc[s >> 1][(s & 1) * 2 + 1], en1);
                if (u0 < m1v[s]) { m2v[s] = m1v[s]; m1v[s] = u0; m1i[s] = g0; }
                else if (u0 < m2v[s]) m2v[s] = u0;
                if (u1 < m1v[s]) { m2v[s] = m1v[s]; m1v[s] = u1; m1i[s] = g0 + 1; }
                else if (u1 < m2v[s]) m2v[s] = u1;
            }
        }
    }

    // reduce across the 4 lanes of each quad (cols ascend with lane&3)
#pragma unroll
    for (int off = 1; off <= 2; off <<= 1) {
#pragma unroll
        for (int s = 0; s < 4; s++) {
            float ov = __shfl_xor_sync(0xffffffffu, m1v[s], off);
            int   oi = __shfl_xor_sync(0xffffffffu, m1i[s], off);
            float o2 = __shfl_xor_sync(0xffffffffu, m2v[s], off);
            float nm2 = fminf(fmaxf(m1v[s], ov), fminf(m2v[s], o2));
            if (ov < m1v[s] || (ov == m1v[s] && oi < m1i[s])) { m1v[s] = ov; m1i[s] = oi; }
            m2v[s] = nm2;
        }
    }
    if ((lane & 3) == 0) {
#pragma unroll
        for (int s = 0; s < 4; s++) {
            int grow = m0 + w * 32 + (lane >> 2) + 8 * s;
            g_idx[grow] = m1i[s];
            if (m2v[s] - m1v[s] < DELTA) {
                int p = atomicAdd(&g_amb_cnt, 1);
                g_amb_rows[p] = grow;
            }
        }
    }
}

// ============================================================
// rescan: EXACT reference arithmetic for ambiguous rows.
//   d = fl( fl(zsq + en) - 2*dot ),  dot = seq ascending-k fmaf.
// First-index argmin (lexicographic (val, idx) reduce).
// ============================================================
__global__ __launch_bounds__(128) void vq_rescan(const float* __restrict__ z,
                                                 const float* __restrict__ emb) {
    __shared__ float zrow[64];
    __shared__ float redv[4];
    __shared__ int   redi[4];
    int tid = threadIdx.x, lane = tid & 31, w = tid >> 5;
    int cnt = g_amb_cnt;

    for (int a = blockIdx.x; a < cnt; a += gridDim.x) {
        int row = g_amb_rows[a];
        if (tid < 64) zrow[tid] = z[row * DIM + tid];
        float zsq = g_zsq[row];
        __syncthreads();

        float bv = FLT_MAX; int bi = 0;
        for (int c = tid; c < NE; c += 128) {       // per-thread codes ascend
            const float* e = emb + c * DIM;
            float dot = 0.0f;
#pragma unroll 16
            for (int k = 0; k < DIM; k++)
                dot = fmaf(zrow[k], e[k], dot);
            float t = __fadd_rn(zsq, g_en[c]);
            float s = __fadd_rn(t, -2.0f * dot);
            if (s < bv) { bv = s; bi = c; }
        }
#pragma unroll
        for (int off = 16; off > 0; off >>= 1) {
            float ov = __shfl_down_sync(0xffffffffu, bv, off);
            int   oi = __shfl_down_sync(0xffffffffu, bi, off);
            if (ov < bv || (ov == bv && oi < bi)) { bv = ov; bi = oi; }
        }
        if (lane == 0) { redv[w] = bv; redi[w] = bi; }
        __syncthreads();
        if (tid == 0) {
            float fv = redv[0]; int fi = redi[0];
#pragma unroll
            for (int q = 1; q < 4; q++) {
                if (redv[q] < fv || (redv[q] == fv && redi[q] < fi)) { fv = redv[q]; fi = redi[q]; }
            }
            g_idx[row] = fi;
        }
        __syncthreads();
    }
}

// ============================================================
// emit: gather z_q, indices, histogram, mse (coalesced).
// ============================================================
__global__ __launch_bounds__(256) void vq_emit(const float* __restrict__ z,
                                               const float* __restrict__ emb,
                                               float* __restrict__ out) {
    __shared__ float red[8];
    int tid = threadIdx.x;
    int m0  = blockIdx.x * 128;
    float* zq   = out + ZQ_OFF;
    float* oidx = out + IDX_OFF;
    int col = tid & 63, r0 = tid >> 6;

    float lsum = 0.0f;
#pragma unroll 4
    for (int it = 0; it < 32; ++it) {
        int r   = m0 + r0 + 4 * it;
        int gi  = r * DIM + col;
        int idx = g_idx[r];
        float q  = emb[idx * DIM + col];
        float zv = z[gi];
        zq[gi] = q;
        float d = q - zv;
        lsum = fmaf(d, d, lsum);
        if (col == 0) {
            oidx[r] = (float)idx;
            atomicAdd(&g_counts[idx], 1.0f);
        }
    }
#pragma unroll
    for (int off = 16; off > 0; off >>= 1)
        lsum += __shfl_down_sync(0xffffffffu, lsum, off);
    if ((tid & 31) == 0) red[tid >> 5] = lsum;
    __syncthreads();
    if (tid == 0) {
        float s = 0.0f;
#pragma unroll
        for (int w = 0; w < 8; w++) s += red[w];
        atomicAdd(&g_mse, (double)s);
    }
}

// ============================================================
// finalize: perplexity + loss scalars (validated).
// ============================================================
__global__ void vq_finalize(float* __restrict__ out) {
    __shared__ float red[32];
    int tid = threadIdx.x;   // 1024 threads
    float p = g_counts[tid] * (1.0f / (float)NROWS);
    float h = -p * logf(p + 1e-10f);
#pragma unroll
    for (int off = 16; off > 0; off >>= 1)
        h += __shfl_down_sync(0xffffffffu, h, off);
    if ((tid & 31) == 0) red[tid >> 5] = h;
    __syncthreads();
    if (tid == 0) {
        float H = 0.0f;
#pragma unroll
        for (int w = 0; w < 32; w++) H += red[w];
        float perp = expf(H);
        double mse = g_mse / (double)(NROWS * DIM);
        double mean_tril = (g_edist * 0.5) / ((double)NE * (double)NE);
        double e_loss = exp(-mean_tril / 0.1);
        out[0]        = (float)(1.25 * mse + e_loss);
        out[PERP_OFF] = perp;
    }
}

// ============================================================
extern "C" void kernel_launch(void* const* d_in, const int* in_sizes, int n_in,
                              void* d_out, int out_size) {
    const float* z   = (const float*)d_in[0];
    const float* emb = (const float*)d_in[1];
    float* out = (float*)d_out;

    const int fsmem = (128 + 256) * LDA * 2 + 256 * 4;   // 105,472 B
    cudaFuncSetAttribute(vq_filter, cudaFuncAttributeMaxDynamicSharedMemorySize, fsmem);

    vq_init<<<1, 1024>>>(emb);
    vq_prep<<<NROWS / 64, 256>>>(z);
    vq_pairs<<<NE / 8, 256>>>(emb);
    vq_filter<<<NROWS / 128, 128, fsmem>>>();
    vq_rescan<<<256, 128>>>(z, emb);
    vq_emit<<<NROWS / 128, 256>>>(z, emb, out);
    vq_finalize<<<1, 1024>>>(out);
}

// round 6
// speedup vs baseline: 2.4710x; 2.4710x over previous
#include <cuda_runtime.h>
#include <cuda_bf16.h>
#include <math.h>
#include <float.h>

#define NROWS 65536      // 32*32*64
#define DIM   64
#define NE    1024
#define LDE   65         // vq_pairs tile ld

// Output layout (float32, return-order flatten)
#define ZQ_OFF   1
#define PERP_OFF (1 + NROWS*DIM)
#define IDX_OFF  (2 + NROWS*DIM)

#define DELTA 4e-5f      // ambiguity margin (> 2*approx_err + 2*ulp(64) window)
#define LDA   136        // padded split-row ld in bf16 (272B = 17*16B)

// ---- scratch (no allocations allowed) ----
__device__ float  g_counts[NE];
__device__ float  g_en[NE];
__device__ float  g_zsq[NROWS];
__device__ int    g_idx[NROWS];
__device__ int    g_amb_rows[NROWS];
__device__ int    g_amb_cnt;
__device__ double g_mse;
__device__ double g_edist;
__device__ __nv_bfloat16 g_esplit[NE * 128];       // [code][ eh(64) | el(64) ]
__device__ __nv_bfloat16 g_zsplit[NROWS * 128];    // [row ][ zh(64) | zl(64) ]

// ============================================================
// PTX helpers (fragment layouts validated bitwise in R5)
// ============================================================
__device__ __forceinline__ void ldmx4(unsigned* r, unsigned addr) {
    asm volatile("ldmatrix.sync.aligned.m8n8.x4.shared.b16 {%0,%1,%2,%3}, [%4];"
                 : "=r"(r[0]), "=r"(r[1]), "=r"(r[2]), "=r"(r[3]) : "r"(addr));
}
__device__ __forceinline__ void mma16816(float* c, const unsigned* a, const unsigned* b) {
    asm volatile("mma.sync.aligned.m16n8k16.row.col.f32.bf16.bf16.f32 "
                 "{%0,%1,%2,%3}, {%4,%5,%6,%7}, {%8,%9}, {%0,%1,%2,%3};"
                 : "+f"(c[0]), "+f"(c[1]), "+f"(c[2]), "+f"(c[3])
                 : "r"(a[0]), "r"(a[1]), "r"(a[2]), "r"(a[3]), "r"(b[0]), "r"(b[1]));
}

// ============================================================
// init v2: coalesced. 16 CTAs x 256 thr, 64 codes/CTA.
// exact ||e||^2 (sequential UNFUSED) + bf16 split + zero accums.
// ============================================================
__global__ __launch_bounds__(256) void vq_init(const float* __restrict__ emb) {
    __shared__ float es[64][65];
    int tid = threadIdx.x;
    int c0  = blockIdx.x * 64;
#pragma unroll
    for (int i = 0; i < 16; i++) {
        int idx = tid + i * 256;
        int r = idx >> 6, c = idx & 63;
        es[r][c] = emb[(c0 + r) * DIM + c];
    }
    if (blockIdx.x == 0) {
#pragma unroll
        for (int q = 0; q < 4; q++) g_counts[tid + q * 256] = 0.0f;
        if (tid == 0) { g_mse = 0.0; g_edist = 0.0; g_amb_cnt = 0; }
    }
    __syncthreads();
    if (tid < 64) {
        float s = 0.0f;
#pragma unroll
        for (int k = 0; k < DIM; k++) {
            float sq = __fmul_rn(es[tid][k], es[tid][k]);
            s = __fadd_rn(s, sq);
        }
        g_en[c0 + tid] = s;
    }
#pragma unroll
    for (int i = 0; i < 16; i++) {
        int idx = tid + i * 256;
        int r = idx >> 6, c = idx & 63;
        float v = es[r][c];
        __nv_bfloat16 h = __float2bfloat16(v);
        __nv_bfloat16 l = __float2bfloat16(v - __bfloat162float(h));
        g_esplit[(c0 + r) * 128 + c]      = h;
        g_esplit[(c0 + r) * 128 + 64 + c] = l;
    }
}

// ============================================================
// prep: exact ||z||^2 per row (sequential UNFUSED) + bf16 split.
// ============================================================
__global__ __launch_bounds__(256) void vq_prep(const float* __restrict__ z) {
    __shared__ float zs[64][65];
    int tid = threadIdx.x;
    int r0  = blockIdx.x * 64;
#pragma unroll
    for (int i = 0; i < 16; i++) {
        int idx = tid + i * 256;
        int r = idx >> 6, c = idx & 63;
        zs[r][c] = z[(r0 + r) * DIM + c];
    }
    __syncthreads();
    if (tid < 64) {
        float s = 0.0f;
#pragma unroll
        for (int k = 0; k < DIM; k++) {
            float sq = __fmul_rn(zs[tid][k], zs[tid][k]);
            s = __fadd_rn(s, sq);
        }
        g_zsq[r0 + tid] = s;
    }
#pragma unroll
    for (int i = 0; i < 16; i++) {
        int idx = tid + i * 256;
        int r = idx >> 6, c = idx & 63;
        float v = zs[r][c];
        __nv_bfloat16 h = __float2bfloat16(v);
        __nv_bfloat16 l = __float2bfloat16(v - __bfloat162float(h));
        g_zsplit[(r0 + r) * 128 + c]      = h;
        g_zsplit[(r0 + r) * 128 + 64 + c] = l;
    }
}

// ============================================================
// codebook pairwise distances (e_loss) — unchanged, validated.
// ============================================================
__global__ __launch_bounds__(256) void vq_pairs(const float* __restrict__ emb) {
    __shared__ float ei[8][DIM];
    __shared__ float ej[128][LDE];
    __shared__ float eni_s[8];
    __shared__ float red[8];
    int tid = threadIdx.x;
    int i0  = blockIdx.x * 8;

    for (int v = tid; v < 8 * DIM; v += 256)
        ei[v >> 6][v & 63] = emb[i0 * DIM + v];
    if (tid < 8) eni_s[tid] = g_en[i0 + tid];

    float sum = 0.0f;
    for (int jc = 0; jc < NE; jc += 128) {
        __syncthreads();
#pragma unroll
        for (int t = 0; t < 8; t++) {
            int v  = tid + t * 256;
            int jl = v >> 4, c4 = (v & 15) << 2;
            float4 f = *reinterpret_cast<const float4*>(emb + (jc + jl) * DIM + c4);
            ej[jl][c4 + 0] = f.x; ej[jl][c4 + 1] = f.y;
            ej[jl][c4 + 2] = f.z; ej[jl][c4 + 3] = f.w;
        }
        __syncthreads();
        int il = tid >> 5, lane = tid & 31;
#pragma unroll
        for (int jj = 0; jj < 4; jj++) {
            int jl = lane + 32 * jj;
            float dot = 0.0f;
#pragma unroll 16
            for (int k = 0; k < DIM; k++)
                dot = fmaf(ei[il][k], ej[jl][k], dot);
            float d2 = eni_s[il] + g_en[jc + jl] - 2.0f * dot;
            sum += sqrtf(fmaxf(d2, 0.0f));
        }
    }
#pragma unroll
    for (int off = 16; off > 0; off >>= 1)
        sum += __shfl_down_sync(0xffffffffu, sum, off);
    if ((tid & 31) == 0) red[tid >> 5] = sum;
    __syncthreads();
    if (tid == 0) {
        float s = 0.0f;
#pragma unroll
        for (int w = 0; w < 8; w++) s += red[w];
        atomicAdd(&g_edist, (double)s);
    }
}

// ============================================================
// filter v2: split-bf16 MMA scoring + per-row (min1,min2).
// 256 thr (8 warps x 16-row mtile) = 128 rows/CTA.
// Codes in 8 chunks of 128; B frags via ldmatrix.x4 (2 ntiles).
// K=192: ks 0-3 zh*eh, 4-7 zh*el, 8-11 zl*eh.
// ============================================================
__global__ __launch_bounds__(256, 2) void vq_filter(void) {
    extern __shared__ __nv_bfloat16 sm[];
    __nv_bfloat16* As = sm;                         // [128][LDA]
    __nv_bfloat16* Bs = sm + 128 * LDA;             // [128][LDA]
    float* en_s = (float*)(sm + 2 * 128 * LDA);     // [128]

    const int tid = threadIdx.x, lane = tid & 31, w = tid >> 5;
    const int m0 = blockIdx.x * 128;

    // stage A (zsplit rows) via uint4: 2048 / 256 thr = 8 each
    const uint4* zsp4 = (const uint4*)g_zsplit;     // 16 uint4 per row
#pragma unroll
    for (int i = 0; i < 8; i++) {
        int idx = tid + i * 256;
        int r = idx >> 4, q = idx & 15;
        *(uint4*)((char*)As + r * (LDA * 2) + q * 16) = zsp4[(m0 + r) * 16 + q];
    }
    __syncthreads();

    // A fragments: f 0-3 = zh k0..63, f 4-7 = zl
    unsigned afr[8][4];
    unsigned abase = (unsigned)__cvta_generic_to_shared(As);
    {
        int arow = w * 16 + (lane & 15);
        int acol8 = (lane >> 4) * 8;
#pragma unroll
        for (int f = 0; f < 8; f++) {
            int aoff = (f < 4) ? 16 * f : 64 + 16 * (f - 4);
            ldmx4(afr[f], abase + (unsigned)(arow * LDA + aoff + acol8) * 2u);
        }
    }

    float m1v[2], m2v[2]; int m1i[2];
#pragma unroll
    for (int s = 0; s < 2; s++) { m1v[s] = FLT_MAX; m2v[s] = FLT_MAX; m1i[s] = 0; }

    unsigned bbase = (unsigned)__cvta_generic_to_shared(Bs);
    const uint4* esp4 = (const uint4*)g_esplit;
    const int brow_in = ((lane >> 4) << 3) + (lane & 7);   // 0..15 pattern
    const int bcol8   = ((lane >> 3) & 1) * 8;
    const int ccol    = 2 * (lane & 3);

    for (int ch = 0; ch < 8; ch++) {
        const int cb = ch * 128;
        __syncthreads();                            // Bs free from previous chunk
#pragma unroll
        for (int i = 0; i < 8; i++) {
            int idx = tid + i * 256;
            int r = idx >> 4, q = idx & 15;
            *(uint4*)((char*)Bs + r * (LDA * 2) + q * 16) = esp4[(cb + r) * 16 + q];
        }
        if (tid < 128) en_s[tid] = g_en[cb + tid];
        __syncthreads();

#pragma unroll 1
        for (int ntp = 0; ntp < 8; ntp++) {         // 16 codes per iter
            float acc0[4] = {0,0,0,0}, acc1[4] = {0,0,0,0};
            const int brow = ntp * 16 + brow_in;
#pragma unroll
            for (int ks = 0; ks < 12; ks++) {
                int f    = (ks < 8) ? (ks & 3) : (4 + (ks & 3));
                int boff = (ks < 4) ? 16 * ks : (ks < 8) ? 64 + 16 * (ks - 4) : 16 * (ks - 8);
                unsigned bf[4];
                ldmx4(bf, bbase + (unsigned)(brow * LDA + boff + bcol8) * 2u);
                mma16816(acc0, afr[f], bf);         // codes ntp*16 + 0..7
                mma16816(acc1, afr[f], bf + 2);     // codes ntp*16 + 8..15
            }
            // epilogue: codes ascend per thread: grp 0 (cols+0..7) then grp 1 (+8..15)
            int l0 = ntp * 16 + ccol;
            float en00 = en_s[l0],     en01 = en_s[l0 + 1];
            float en10 = en_s[l0 + 8], en11 = en_s[l0 + 9];
            int g00 = cb + l0, g10 = cb + l0 + 8;
#pragma unroll
            for (int s = 0; s < 2; s++) {           // s=0: row lane>>2 ; s=1: +8
                float u0 = fmaf(-2.0f, acc0[2 * s],     en00);
                float u1 = fmaf(-2.0f, acc0[2 * s + 1], en01);
                float u2 = fmaf(-2.0f, acc1[2 * s],     en10);
                float u3 = fmaf(-2.0f, acc1[2 * s + 1], en11);
                if (u0 < m1v[s]) { m2v[s] = m1v[s]; m1v[s] = u0; m1i[s] = g00; }
                else if (u0 < m2v[s]) m2v[s] = u0;
                if (u1 < m1v[s]) { m2v[s] = m1v[s]; m1v[s] = u1; m1i[s] = g00 + 1; }
                else if (u1 < m2v[s]) m2v[s] = u1;
                if (u2 < m1v[s]) { m2v[s] = m1v[s]; m1v[s] = u2; m1i[s] = g10; }
                else if (u2 < m2v[s]) m2v[s] = u2;
                if (u3 < m1v[s]) { m2v[s] = m1v[s]; m1v[s] = u3; m1i[s] = g10 + 1; }
                else if (u3 < m2v[s]) m2v[s] = u3;
            }
        }
    }

    // quad reduce (cols live in lanes xor 1,2); lexicographic (val, idx)
#pragma unroll
    for (int off = 1; off <= 2; off <<= 1) {
#pragma unroll
        for (int s = 0; s < 2; s++) {
            float ov = __shfl_xor_sync(0xffffffffu, m1v[s], off);
            int   oi = __shfl_xor_sync(0xffffffffu, m1i[s], off);
            float o2 = __shfl_xor_sync(0xffffffffu, m2v[s], off);
            float nm2 = fminf(fmaxf(m1v[s], ov), fminf(m2v[s], o2));
            if (ov < m1v[s] || (ov == m1v[s] && oi < m1i[s])) { m1v[s] = ov; m1i[s] = oi; }
            m2v[s] = nm2;
        }
    }
    if ((lane & 3) == 0) {
#pragma unroll
        for (int s = 0; s < 2; s++) {
            int grow = m0 + w * 16 + (lane >> 2) + 8 * s;
            g_idx[grow] = m1i[s];
            if (m2v[s] - m1v[s] < DELTA) {
                int p = atomicAdd(&g_amb_cnt, 1);
                g_amb_rows[p] = grow;
            }
        }
    }
}

// ============================================================
// rescan v2: EXACT reference arithmetic, ONE WARP PER ROW.
//   d = fl( fl(zsq + en) - 2*dot ),  dot = seq ascending-k fmaf.
// Per-lane codes ascend; lexicographic cross-lane reduce.
// ============================================================
__global__ __launch_bounds__(256) void vq_rescan(const float* __restrict__ z,
                                                 const float* __restrict__ emb) {
    __shared__ float zr[8][64];
    int tid = threadIdx.x, lane = tid & 31, w = tid >> 5;
    int wg = blockIdx.x * 8 + w;
    int nW = gridDim.x * 8;
    int cnt = g_amb_cnt;

    for (int a = wg; a < cnt; a += nW) {
        int row = g_amb_rows[a];
        float2 zv = *(const float2*)(z + row * DIM + 2 * lane);
        zr[w][2 * lane] = zv.x; zr[w][2 * lane + 1] = zv.y;
        __syncwarp();
        float zsq = g_zsq[row];

        float bv = FLT_MAX; int bi = 0;
        for (int c = lane; c < NE; c += 32) {       // per-lane codes ascend
            const float4* e4 = (const float4*)(emb + c * DIM);
            float dot = 0.0f;
#pragma unroll
            for (int k4 = 0; k4 < 16; k4++) {
                float4 ev = __ldg(&e4[k4]);
                dot = fmaf(zr[w][4 * k4 + 0], ev.x, dot);
                dot = fmaf(zr[w][4 * k4 + 1], ev.y, dot);
                dot = fmaf(zr[w][4 * k4 + 2], ev.z, dot);
                dot = fmaf(zr[w][4 * k4 + 3], ev.w, dot);
            }
            float t = __fadd_rn(zsq, g_en[c]);
            float s = __fadd_rn(t, -2.0f * dot);
            if (s < bv) { bv = s; bi = c; }
        }
#pragma unroll
        for (int off = 16; off > 0; off >>= 1) {
            float ov = __shfl_down_sync(0xffffffffu, bv, off);
            int   oi = __shfl_down_sync(0xffffffffu, bi, off);
            if (ov < bv || (ov == bv && oi < bi)) { bv = ov; bi = oi; }
        }
        if (lane == 0) g_idx[row] = bi;
        __syncwarp();
    }
}

// ============================================================
// emit: gather z_q, indices, histogram, mse (coalesced).
// ============================================================
__global__ __launch_bounds__(256) void vq_emit(const float* __restrict__ z,
                                               const float* __restrict__ emb,
                                               float* __restrict__ out) {
    __shared__ float red[8];
    int tid = threadIdx.x;
    int m0  = blockIdx.x * 128;
    float* zq   = out + ZQ_OFF;
    float* oidx = out + IDX_OFF;
    int col = tid & 63, r0 = tid >> 6;

    float lsum = 0.0f;
#pragma unroll 4
    for (int it = 0; it < 32; ++it) {
        int r   = m0 + r0 + 4 * it;
        int gi  = r * DIM + col;
        int idx = g_idx[r];
        float q  = emb[idx * DIM + col];
        float zv = z[gi];
        zq[gi] = q;
        float d = q - zv;
        lsum = fmaf(d, d, lsum);
        if (col == 0) {
            oidx[r] = (float)idx;
            atomicAdd(&g_counts[idx], 1.0f);
        }
    }
#pragma unroll
    for (int off = 16; off > 0; off >>= 1)
        lsum += __shfl_down_sync(0xffffffffu, lsum, off);
    if ((tid & 31) == 0) red[tid >> 5] = lsum;
    __syncthreads();
    if (tid == 0) {
        float s = 0.0f;
#pragma unroll
        for (int w = 0; w < 8; w++) s += red[w];
        atomicAdd(&g_mse, (double)s);
    }
}

// ============================================================
// finalize: perplexity + loss scalars (validated).
// ============================================================
__global__ void vq_finalize(float* __restrict__ out) {
    __shared__ float red[32];
    int tid = threadIdx.x;   // 1024 threads
    float p = g_counts[tid] * (1.0f / (float)NROWS);
    float h = -p * logf(p + 1e-10f);
#pragma unroll
    for (int off = 16; off > 0; off >>= 1)
        h += __shfl_down_sync(0xffffffffu, h, off);
    if ((tid & 31) == 0) red[tid >> 5] = h;
    __syncthreads();
    if (tid == 0) {
        float H = 0.0f;
#pragma unroll
        for (int w = 0; w < 32; w++) H += red[w];
        float perp = expf(H);
        double mse = g_mse / (double)(NROWS * DIM);
        double mean_tril = (g_edist * 0.5) / ((double)NE * (double)NE);
        double e_loss = exp(-mean_tril / 0.1);
        out[0]        = (float)(1.25 * mse + e_loss);
        out[PERP_OFF] = perp;
    }
}

// ============================================================
extern "C" void kernel_launch(void* const* d_in, const int* in_sizes, int n_in,
                              void* d_out, int out_size) {
    const float* z   = (const float*)d_in[0];
    const float* emb = (const float*)d_in[1];
    float* out = (float*)d_out;

    const int fsmem = 2 * 128 * LDA * 2 + 128 * 4;   // 70,144 B
    cudaFuncSetAttribute(vq_filter, cudaFuncAttributeMaxDynamicSharedMemorySize, fsmem);

    vq_init<<<NE / 64, 256>>>(emb);
    vq_prep<<<NROWS / 64, 256>>>(z);
    vq_pairs<<<NE / 8, 256>>>(emb);
    vq_filter<<<NROWS / 128, 256, fsmem>>>();
    vq_rescan<<<128, 256>>>(z, emb);
    vq_emit<<<NROWS / 128, 256>>>(z, emb, out);
    vq_finalize<<<1, 1024>>>(out);
}